// round 8
// baseline (speedup 1.0000x reference)
#include <cuda_runtime.h>
#include <cuda_bf16.h>
#include <cstdint>

#define DIM 4096
#define THREADS 128
#define SROW 36   // padded stride (words) per 32-word group: conflict-free both patterns

// In-register 32-point Walsh-Hadamard (unnormalized butterflies).
__device__ __forceinline__ void fwht32(float r[32]) {
#pragma unroll
    for (int h = 1; h < 32; h <<= 1) {
#pragma unroll
        for (int k = 0; k < 32; k++) {
            if ((k & h) == 0) {
                float a = r[k];
                float b = r[k + h];
                r[k]     = a + b;
                r[k + h] = a - b;
            }
        }
    }
}

__global__ __launch_bounds__(THREADS, 10)   // R4's proven reg/occ balance (48 regs)
void fwht4096_kernel(const float* __restrict__ x, float* __restrict__ y) {
    // Logical element i (12 bits) stored at phys(i) = (i>>5)*SROW + (i&31).
    __shared__ float s[128 * SROW];   // 18432 B

    const int t    = threadIdx.x;
    const int w    = t >> 5;
    const int lane = t & 31;

    const float* xr = x + (size_t)blockIdx.x * DIM;
    float*       yr = y + (size_t)blockIdx.x * DIM;

    float r[32];

    // ---- Load: r[k] = x[k*128 + t]. Per warp per k: one contiguous 128B line
    // (sector-perfect). 32 independent loads -> deep MLP.
#pragma unroll
    for (int k = 0; k < 32; k++)
        r[k] = xr[k * 128 + t];

    // ---- Phase A: butterflies over i bits 7..11 (== bits of k).
    fwht32(r);

    // ---- Exchange write: i = k*128 + t  ->  phys = (4k + w)*36 + lane.
    // Banks (16k + 4w + lane) mod 32: distinct per lane -> conflict-free.
#pragma unroll
    for (int k = 0; k < 32; k++)
        s[(4 * k + w) * SROW + lane] = r[k];
    __syncthreads();

    // ---- Exchange read: thread t owns i = c + (t&3)*32 + (t>>2)*128, c=0..31.
    // i>>5 == t, so phys = t*36 + c : contiguous, 144B-aligned -> 8x LDS.128.
    // Banks 4(t+m) mod 32: disjoint per quarter-warp -> conflict-free.
    {
        const float4* s4 = reinterpret_cast<const float4*>(&s[t * SROW]);
#pragma unroll
        for (int m = 0; m < 8; m++) {
            float4 v = s4[m];
            r[4*m+0] = v.x; r[4*m+1] = v.y; r[4*m+2] = v.z; r[4*m+3] = v.w;
        }
    }

    // ---- Phase B part 1: butterflies over i bits 0..4 (== bits of c).
    fwht32(r);

    // ---- Phase B part 2: bits 5,6 of i live in lane bits 0,1 -> shuffle stages.
    {
        const float sgn5 = (t & 1) ? -1.0f : 1.0f;
#pragma unroll
        for (int k = 0; k < 32; k++) {
            float o = __shfl_xor_sync(0xFFFFFFFFu, r[k], 1);
            r[k] = fmaf(sgn5, r[k], o);   // low: a+b, high: a-b
        }
        const float sgn6 = (t & 2) ? -1.0f : 1.0f;
#pragma unroll
        for (int k = 0; k < 32; k++) {
            float o = __shfl_xor_sync(0xFFFFFFFFu, r[k], 2);
            r[k] = fmaf(sgn6, r[k], o);
        }
    }

    // ---- Direct store: thread t holds output elements
    // i = (t>>2)*128 + (t&3)*32 + c for c = 0..31 -> 32 CONTIGUOUS elements.
    // 8x STG.128, each writing 16 distinct full sectors; warp covers 4KB
    // contiguous. No exchange-2 needed. Scale 1/sqrt(4096) = 1/64 (exact).
    const float sc = 0.015625f;
    {
        float4* y4 = reinterpret_cast<float4*>(yr) + ((t >> 2) * 32 + (t & 3) * 8);
#pragma unroll
        for (int m = 0; m < 8; m++) {
            float4 v;
            v.x = r[4*m+0] * sc;
            v.y = r[4*m+1] * sc;
            v.z = r[4*m+2] * sc;
            v.w = r[4*m+3] * sc;
            y4[m] = v;
        }
    }
}

extern "C" void kernel_launch(void* const* d_in, const int* in_sizes, int n_in,
                              void* d_out, int out_size) {
    const float* x = (const float*)d_in[0];
    float* y = (float*)d_out;
    const int n = in_sizes[0];
    const int rows = n / DIM;   // 8192
    fwht4096_kernel<<<rows, THREADS>>>(x, y);
}

// round 11
// speedup vs baseline: 1.4522x; 1.4522x over previous
#include <cuda_runtime.h>
#include <cuda_bf16.h>
#include <cstdint>

#define DIM 4096
#define THREADS 128
#define SROW 36   // padded stride (words) per 32-element group; conflict-free everywhere

// In-register 32-point Walsh-Hadamard (unnormalized butterflies).
__device__ __forceinline__ void fwht32(float r[32]) {
#pragma unroll
    for (int h = 1; h < 32; h <<= 1) {
#pragma unroll
        for (int k = 0; k < 32; k++) {
            if ((k & h) == 0) {
                float a = r[k];
                float b = r[k + h];
                r[k]     = a + b;
                r[k + h] = a - b;
            }
        }
    }
}

__global__ __launch_bounds__(THREADS, 10)   // R4's proven reg/occ balance
void fwht4096_kernel(const float* __restrict__ x, float* __restrict__ y) {
    // Global element i (12 bits) lives at phys(i) = (i>>5)*SROW + (i&31).
    __shared__ float s[128 * SROW];   // 18432 B

    const int t    = threadIdx.x;
    const int w    = t >> 5;
    const int lane = t & 31;

    const float* xr = x + (size_t)blockIdx.x * DIM;
    float*       yr = y + (size_t)blockIdx.x * DIM;

    float r[32];

    // ---- Load: r[k] = x[k*128 + t]. One contiguous 128B line per warp per k
    // (sector-perfect); 32 independent loads -> deep MLP.
#pragma unroll
    for (int k = 0; k < 32; k++)
        r[k] = xr[k * 128 + t];

    // ---- Phase A: butterflies over i bits 7..11 (== bits of k).
    fwht32(r);

    // ---- Exchange 1 write: i = k*128 + t -> phys = (4k + w)*36 + lane.
    // Banks (16k + 4w + lane) mod 32 distinct per lane -> conflict-free.
#pragma unroll
    for (int k = 0; k < 32; k++)
        s[(4 * k + w) * SROW + lane] = r[k];
    __syncthreads();

    // ---- Exchange 1 read: thread t owns i = t*32 + c, c = 0..31 (contiguous).
    // phys = t*36 + c: 144B-aligned rows -> 8x LDS.128; banks 4(t+m) disjoint
    // per quarter-warp -> conflict-free.
    {
        const float4* s4 = reinterpret_cast<const float4*>(&s[t * SROW]);
#pragma unroll
        for (int m = 0; m < 8; m++) {
            float4 v = s4[m];
            r[4*m+0] = v.x; r[4*m+1] = v.y; r[4*m+2] = v.z; r[4*m+3] = v.w;
        }
    }

    // ---- Phase B: butterflies over i bits 0..4 (== bits of c).
    fwht32(r);

    // ---- Exchange 2 write: back into the SAME row [36t, 36t+32) this thread
    // just read -> no barrier needed before this write. 8x STS.128, CF.
    {
        float4* s4 = reinterpret_cast<float4*>(&s[t * SROW]);
#pragma unroll
        for (int m = 0; m < 8; m++) {
            float4 v;
            v.x = r[4*m+0]; v.y = r[4*m+1]; v.z = r[4*m+2]; v.w = r[4*m+3];
            s4[m] = v;
        }
    }
    __syncthreads();

    // ---- Exchange 2 read: reg d owns i with bits{5,6}=d bits{0,1},
    // bits{7,8,9}=d bits{2,3,4}, bits{10,11}=w, bits{0..4}=lane.
    // i>>5 = d + 32*w  ->  phys = (d + 32*w)*36 + lane.
    // Banks (4d + lane) mod 32 distinct per lane -> conflict-free.
#pragma unroll
    for (int d = 0; d < 32; d++)
        r[d] = s[(d + 32 * w) * SROW + lane];

    // ---- Phase C: butterflies over i bits 5,6 (== d bits 0,1) in registers
    // (replaces the shuffle stages: -64 LSU wavefronts per warp).
#pragma unroll
    for (int d = 0; d < 32; d += 2) {
        float a = r[d], b = r[d + 1];
        r[d]     = a + b;
        r[d + 1] = a - b;
    }
#pragma unroll
    for (int d = 0; d < 32; d++) {
        if ((d & 2) == 0) {
            float a = r[d], b = r[d + 2];
            r[d]     = a + b;
            r[d + 2] = a - b;
        }
    }

    // ---- Store: i = lane + (d&3)*32 + (d>>2)*128 + w*1024.
    // Fixed d: lanes sweep i bits 0..4 -> one contiguous 128B line. Coalesced.
    const float sc = 0.015625f;   // 1/sqrt(4096), exact
    float* yw = yr + (w << 10) + lane;
#pragma unroll
    for (int d = 0; d < 32; d++)
        yw[((d & 3) << 5) + ((d >> 2) << 7)] = r[d] * sc;
}

extern "C" void kernel_launch(void* const* d_in, const int* in_sizes, int n_in,
                              void* d_out, int out_size) {
    const float* x = (const float*)d_in[0];
    float* y = (float*)d_out;
    const int n = in_sizes[0];
    const int rows = n / DIM;   // 8192
    fwht4096_kernel<<<rows, THREADS>>>(x, y);
}